// round 10
// baseline (speedup 1.0000x reference)
#include <cuda_runtime.h>
#include <cuda_bf16.h>
#include <cstdint>
#include <cstddef>

#define BATCH 8
#define NPTS  4096
#define NS    1024
#define DIMF  32

// ----------------------------- static device scratch -----------------------------
__device__ float4 g_pxyz[BATCH * NPTS];          // x,y,z,|p|^2
__device__ float4 g_cent[BATCH * NS];            // centers x,y,z,|c|^2
__device__ int    g_idxAll[3 * BATCH * NS * 64]; // ball-query indices, stride 64
__device__ float  g_y1[67108864];                // up to 524288 x 128
__device__ float  g_gmax[3][8192][256];          // per-scale group-max (pre-BN2)
__device__ double g_sum[6][256];
__device__ double g_sq[6][256];
__device__ float  g_bnA[6][256];
__device__ float  g_bnB[6][256];
__device__ __align__(16) __nv_bfloat16 g_w2t_hi[3][32768]; // W2^T hi split [n*K+k]
__device__ __align__(16) __nv_bfloat16 g_w2t_lo[3][32768]; // W2^T lo split

__device__ __forceinline__ uint32_t smem_u32(const void* p) {
    uint32_t a;
    asm("{ .reg .u64 t; cvta.to.shared.u64 t, %1; cvt.u32.u64 %0, t; }" : "=r"(a) : "l"(p));
    return a;
}

// ----------------------------- init: zero BN stats + pack xyz -----------------------------
__global__ void initpack_kernel(const float* __restrict__ xyz) {
    int i = blockIdx.x * 256 + threadIdx.x;
    if (i < BATCH * NPTS) {
        float x = xyz[3 * i], y = xyz[3 * i + 1], z = xyz[3 * i + 2];
        float nb = __fadd_rn(__fadd_rn(__fmul_rn(x, x), __fmul_rn(y, y)), __fmul_rn(z, z));
        g_pxyz[i] = make_float4(x, y, z, nb);
    }
    if (blockIdx.x == 0) {
        int t = threadIdx.x;
        for (int s = 0; s < 6; s++) { g_sum[s][t] = 0.0; g_sq[s][t] = 0.0; }
    }
}

// ----------------------------- W2 transpose + bf16 split prep -----------------------------
__global__ void w2prep_kernel(const float* __restrict__ W2, int K, int C2, int sc) {
    int idx = blockIdx.x * 256 + threadIdx.x;
    if (idx < K * C2) {
        int n = idx / K, k = idx % K;
        float v = W2[(size_t)k * C2 + n];
        __nv_bfloat16 h = __float2bfloat16_rn(v);
        float lo = v - __bfloat162float(h);
        g_w2t_hi[sc][idx] = h;
        g_w2t_lo[sc][idx] = __float2bfloat16_rn(lo);
    }
}

// ----------------------------- farthest point sampling (R5 two-barrier version) ---------------
__global__ void __launch_bounds__(512) fps_kernel(const float* __restrict__ xyz) {
    const int b = blockIdx.x;
    const float* base = xyz + (size_t)b * NPTS * 3;
    const int t = threadIdx.x, lane = t & 31, warp = t >> 5;

    float px[8], py[8], pz[8], dist[8];
#pragma unroll
    for (int j = 0; j < 8; j++) {
        int p = t + j * 512;
        px[j] = base[3 * p]; py[j] = base[3 * p + 1]; pz[j] = base[3 * p + 2];
        dist[j] = 1e10f;
    }

    __shared__ float s_v[16];
    __shared__ int   s_i[16];
    __shared__ float s_x[2][16], s_y[2][16], s_z[2][16];
    __shared__ int   s_w;

    float cx = base[0], cy = base[1], cz = base[2];

    for (int it = 0; it < NS; it++) {
        const int pb = it & 1;
        if (t == 0) {
            float nrm = __fadd_rn(__fadd_rn(__fmul_rn(cx, cx), __fmul_rn(cy, cy)), __fmul_rn(cz, cz));
            g_cent[b * NS + it] = make_float4(cx, cy, cz, nrm);
        }
        float bv = -1.0f; int bi = 0x7fffffff;
#pragma unroll
        for (int j = 0; j < 8; j++) {
            float dx = __fsub_rn(px[j], cx);
            float dy = __fsub_rn(py[j], cy);
            float dz = __fsub_rn(pz[j], cz);
            float d  = __fadd_rn(__fadd_rn(__fmul_rn(dx, dx), __fmul_rn(dy, dy)), __fmul_rn(dz, dz));
            float nd = fminf(dist[j], d);
            dist[j] = nd;
            if (nd > bv) { bv = nd; bi = t + j * 512; }
        }
#pragma unroll
        for (int off = 16; off > 0; off >>= 1) {
            float ov = __shfl_xor_sync(0xffffffffu, bv, off);
            int   oi = __shfl_xor_sync(0xffffffffu, bi, off);
            if (ov > bv || (ov == bv && oi < bi)) { bv = ov; bi = oi; }
        }
        if ((bi & 31) == lane) {
            int j = bi >> 9;
            float ox = px[0], oy = py[0], oz = pz[0];
#pragma unroll
            for (int jj = 1; jj < 8; jj++)
                if (j == jj) { ox = px[jj]; oy = py[jj]; oz = pz[jj]; }
            s_v[warp] = bv; s_i[warp] = bi;
            s_x[pb][warp] = ox; s_y[pb][warp] = oy; s_z[pb][warp] = oz;
        }
        __syncthreads();
        if (warp == 0) {
            float v  = (lane < 16) ? s_v[lane] : -2.0f;
            int   i2 = (lane < 16) ? s_i[lane] : 0x7fffffff;
#pragma unroll
            for (int off = 8; off > 0; off >>= 1) {
                float ov = __shfl_xor_sync(0xffffffffu, v, off);
                int   oi = __shfl_xor_sync(0xffffffffu, i2, off);
                if (ov > v || (ov == v && oi < i2)) { v = ov; i2 = oi; }
            }
            if (lane == 0) s_w = (i2 & 511) >> 5;
        }
        __syncthreads();
        int w2 = s_w;
        cx = s_x[pb][w2]; cy = s_y[pb][w2]; cz = s_z[pb][w2];
    }
}

// copy new_xyz from g_cent into d_out
__global__ void copyxyz_kernel(float* __restrict__ out) {
    int i = blockIdx.x * 256 + threadIdx.x;
    if (i < BATCH * NS) {
        float4 c = g_cent[i];
        out[3 * i] = c.x; out[3 * i + 1] = c.y; out[3 * i + 2] = c.z;
    }
}

// ----------------------------- ball query (3 scales, unchanged) -----------------------------
__global__ void __launch_bounds__(256) ballquery_kernel() {
    const int scale = blockIdx.y;
    const float r2 = (scale == 0) ? 0.01f : (scale == 1) ? 0.04f : 0.16f;
    const int K = 16 << scale;
    const int t = threadIdx.x, lane = t & 31, warp = t >> 5;
    const int g = blockIdx.x * 8 + warp;
    const int b = g >> 10;
    float4 c = g_cent[g];
    int* out = g_idxAll + scale * (BATCH * NS * 64) + g * 64;
    const float4* P = g_pxyz + ((size_t)b << 12);

    int cnt = 0, firstIdx = 0;
    for (int ch = 0; ch < NPTS / 32; ch++) {
        int p = (ch << 5) + lane;
        float4 q = P[p];
        float dot = __fadd_rn(__fadd_rn(__fmul_rn(c.x, q.x), __fmul_rn(c.y, q.y)), __fmul_rn(c.z, q.z));
        float d = __fsub_rn(__fadd_rn(c.w, q.w), __fadd_rn(dot, dot));
        bool ok = (d <= r2);
        unsigned mask = __ballot_sync(0xffffffffu, ok);
        if (mask) {
            if (cnt == 0) firstIdx = (ch << 5) + (__ffs(mask) - 1);
            if (ok) {
                int pos = cnt + __popc(mask & ((1u << lane) - 1u));
                if (pos < K) out[pos] = p;
            }
            cnt += __popc(mask);
            if (cnt >= K) break;
        }
    }
    if (cnt < K) {
        for (int i = cnt + lane; i < K; i += 32) out[i] = firstIdx;
    }
}

// ----------------------------- GEMM1: fused gather + feat@W1 + b1, BN stats (R5 version) ------
template<int C1, int KLOG, int SCALE, int SLOT>
__global__ void __launch_bounds__(256) gemm1_kernel(const float* __restrict__ points,
                                                    const float* __restrict__ W,
                                                    const float* __restrict__ bias) {
    constexpr int KS = 1 << KLOG;
    constexpr int CT = C1 / 4;
    constexpr int RG = 256 / CT;
    constexpr int RT = 64 / RG;
    __shared__ float sA[64][36];
    __shared__ float sW[35][C1];
    __shared__ float sBias[C1];

    const int tid = threadIdx.x;
    const int r0 = blockIdx.x * 64;

    {
        int row = tid >> 2, sub = tid & 3;
        int gr = r0 + row;
        int b = gr >> (10 + KLOG);
        int s = (gr >> KLOG) & 1023;
        int k = gr & (KS - 1);
        int g = (b << 10) + s;
        int idx = g_idxAll[SCALE * (BATCH * NS * 64) + g * 64 + k];
        if (sub == 0) {
            float4 p = g_pxyz[(b << 12) + idx];
            float4 c = g_cent[g];
            sA[row][0] = p.x - c.x; sA[row][1] = p.y - c.y; sA[row][2] = p.z - c.z;
        }
        const float4* p4 = (const float4*)(points + ((((size_t)(b << 12)) + idx) << 5));
        float4 v0 = p4[sub * 2], v1 = p4[sub * 2 + 1];
        int cb = 3 + sub * 8;
        sA[row][cb + 0] = v0.x; sA[row][cb + 1] = v0.y; sA[row][cb + 2] = v0.z; sA[row][cb + 3] = v0.w;
        sA[row][cb + 4] = v1.x; sA[row][cb + 5] = v1.y; sA[row][cb + 6] = v1.z; sA[row][cb + 7] = v1.w;
    }
    for (int i = tid; i < 35 * C1; i += 256) sW[i / C1][i % C1] = W[i];
    if (tid < C1) sBias[tid] = bias[tid];
    __syncthreads();

    const int tx = tid % CT, ty = tid / CT;
    float acc[RT][4];
#pragma unroll
    for (int i = 0; i < RT; i++) { acc[i][0] = 0.f; acc[i][1] = 0.f; acc[i][2] = 0.f; acc[i][3] = 0.f; }

#pragma unroll
    for (int k = 0; k < 35; k++) {
        float4 w = *(const float4*)&sW[k][tx * 4];
#pragma unroll
        for (int i = 0; i < RT; i++) {
            float a = sA[ty * RT + i][k];
            acc[i][0] = fmaf(a, w.x, acc[i][0]);
            acc[i][1] = fmaf(a, w.y, acc[i][1]);
            acc[i][2] = fmaf(a, w.z, acc[i][2]);
            acc[i][3] = fmaf(a, w.w, acc[i][3]);
        }
    }

    float4 bb = *(const float4*)&sBias[tx * 4];
    float lsum[4] = {0.f, 0.f, 0.f, 0.f}, lsq[4] = {0.f, 0.f, 0.f, 0.f};
#pragma unroll
    for (int i = 0; i < RT; i++) {
        float4 v;
        v.x = acc[i][0] + bb.x; v.y = acc[i][1] + bb.y;
        v.z = acc[i][2] + bb.z; v.w = acc[i][3] + bb.w;
        *(float4*)&g_y1[((size_t)(r0 + ty * RT + i)) * C1 + tx * 4] = v;
        lsum[0] += v.x; lsq[0] += v.x * v.x;
        lsum[1] += v.y; lsq[1] += v.y * v.y;
        lsum[2] += v.z; lsq[2] += v.z * v.z;
        lsum[3] += v.w; lsq[3] += v.w * v.w;
    }
    __syncthreads();
    float* csum = &sA[0][0];
    float* csq  = csum + C1;
    if (tid < C1) { csum[tid] = 0.f; csq[tid] = 0.f; }
    __syncthreads();
#pragma unroll
    for (int j = 0; j < 4; j++) {
        atomicAdd(&csum[tx * 4 + j], lsum[j]);
        atomicAdd(&csq[tx * 4 + j], lsq[j]);
    }
    __syncthreads();
    if (tid < C1) {
        atomicAdd(&g_sum[SLOT][tid], (double)csum[tid]);
        atomicAdd(&g_sq[SLOT][tid],  (double)csq[tid]);
    }
}

// ----------------------------- BN finalize -----------------------------
__global__ void bnfin_kernel(int slot, int C, double invCount,
                             const float* __restrict__ gamma,
                             const float* __restrict__ beta) {
    int c = threadIdx.x;
    if (c < C) {
        double mean = g_sum[slot][c] * invCount;
        double var  = g_sq[slot][c] * invCount - mean * mean;
        float a = gamma[c] * rsqrtf((float)var + 1e-5f);
        g_bnA[slot][c] = a;
        g_bnB[slot][c] = beta[c] - (float)mean * a;
    }
}

// ----------------------------- GEMM2 v2: k-chunked double-buffered mma.sync bf16x3 -------------
// 32-k chunks, 2 buffers (64KB total tiles); 2 CTAs/SM. Per chunk: prefetch next A (regs),
// 3 passes x 2 ksteps x 16 mma, then convert+STS next chunk, 1 barrier.
__device__ __forceinline__ void mma_bf16(float* c, const uint32_t* a, const uint32_t* b) {
    asm volatile("mma.sync.aligned.m16n8k16.row.col.f32.bf16.bf16.f32 "
                 "{%0,%1,%2,%3}, {%4,%5,%6,%7}, {%8,%9}, {%0,%1,%2,%3};"
                 : "+f"(c[0]), "+f"(c[1]), "+f"(c[2]), "+f"(c[3])
                 : "r"(a[0]), "r"(a[1]), "r"(a[2]), "r"(a[3]), "r"(b[0]), "r"(b[1]));
}
__device__ __forceinline__ void ldsm4(uint32_t* r, uint32_t addr) {
    asm volatile("ldmatrix.sync.aligned.m8n8.x4.shared.b16 {%0,%1,%2,%3}, [%4];"
                 : "=r"(r[0]), "=r"(r[1]), "=r"(r[2]), "=r"(r[3]) : "r"(addr));
}
// swizzled 16B-unit offset inside an 8KB chunk tile (128 rows x 4 units)
__device__ __forceinline__ uint32_t chunk_off(int row, int ku) {
    return ((uint32_t)row << 6) + (uint32_t)((ku ^ ((row >> 1) & 3)) << 4);
}

template<int K, int KGRP, int SLOT1, int SLOT2, int SC>
__global__ void __launch_bounds__(256, 2) gemm2_mma(const float* __restrict__ bias2) {
    extern __shared__ char smem[];
    constexpr int NCH = K / 32;          // chunks
    constexpr int TB = 8192;             // bytes per chunk tile (128 x 32 bf16)
    // buffer b: A_HI = b*32768, A_LO = +8192, B_HI = +16384, B_LO = +24576
    float* sEpi = (float*)smem;          // [128][132], aliases buffers post-mainloop

    __shared__ float sBias[128];
    __shared__ float sG[8][128];
    __shared__ float sSum[128];
    __shared__ float sSq[128];

    const int tid = threadIdx.x;
    const int wid = tid >> 5, lane = tid & 31;
    const int r0 = blockIdx.x * 128;
    const int c0 = blockIdx.y * 128;
    const uint32_t sbase = smem_u32(smem);

    if (tid < 128) { sBias[tid] = bias2[c0 + tid]; sSum[tid] = 0.f; sSq[tid] = 0.f; }

    const int srow = tid >> 2, sku = tid & 3;   // staging slot (this thread's 2 slots: +0, +64 rows)

    // ---- stage helper pieces (A: BN1+ReLU+split; B: preconverted) ----
    union Pack { __nv_bfloat16 h[8]; uint4 u; };
    auto cvt_store_A = [&](int buf, int ck, const float4& v0, const float4& v1, int row, int ku) {
        float f[8] = {v0.x, v0.y, v0.z, v0.w, v1.x, v1.y, v1.z, v1.w};
        int kb = ck + ku * 8;
        Pack ph, pl;
#pragma unroll
        for (int j = 0; j < 8; j++) {
            float v = fmaxf(fmaf(f[j], g_bnA[SLOT1][kb + j], g_bnB[SLOT1][kb + j]), 0.f);
            __nv_bfloat16 h = __float2bfloat16_rn(v);
            ph.h[j] = h;
            pl.h[j] = __float2bfloat16_rn(v - __bfloat162float(h));
        }
        uint32_t off = chunk_off(row, ku);
        *(uint4*)(smem + buf * 32768 + off) = ph.u;
        *(uint4*)(smem + buf * 32768 + TB + off) = pl.u;
    };
    auto stage_B = [&](int buf, int ck) {
#pragma unroll
        for (int s = 0; s < 2; s++) {
            int row = srow + s * 64;
            uint32_t off = chunk_off(row, sku);
            size_t gi = (size_t)(c0 + row) * K + ck + sku * 8;
            *(uint4*)(smem + buf * 32768 + 2 * TB + off) = *(const uint4*)&g_w2t_hi[SC][gi];
            *(uint4*)(smem + buf * 32768 + 3 * TB + off) = *(const uint4*)&g_w2t_lo[SC][gi];
        }
    };

    // ---- stage chunk 0 ----
    {
#pragma unroll
        for (int s = 0; s < 2; s++) {
            int row = srow + s * 64;
            const float* yp = &g_y1[(size_t)(r0 + row) * K + sku * 8];
            float4 v0 = *(const float4*)yp;
            float4 v1 = *(const float4*)(yp + 4);
            cvt_store_A(0, 0, v0, v1, row, sku);
        }
        stage_B(0, 0);
    }
    __syncthreads();

    // ---- warp tiling (identical to R5): 2(M) x 4(N) warps, 64x32 per warp ----
    const int wm = wid >> 2, wn = wid & 3;
    const int m_base = wm * 64, n_base = wn * 32;
    const int mat = lane >> 3, r8 = lane & 7;
    int a_row[4], b_row[2];
    const int a_ke = mat >> 1;
    const int b_ke = mat & 1;
#pragma unroll
    for (int f = 0; f < 4; f++) a_row[f] = m_base + f * 16 + (mat & 1) * 8 + r8;
#pragma unroll
    for (int j = 0; j < 2; j++) b_row[j] = n_base + 16 * j + (mat >> 1) * 8 + r8;

    float acc[4][4][4];
#pragma unroll
    for (int mf = 0; mf < 4; mf++)
#pragma unroll
        for (int nf = 0; nf < 4; nf++)
#pragma unroll
            for (int q = 0; q < 4; q++) acc[mf][nf][q] = 0.f;

#pragma unroll 1
    for (int c = 0; c < NCH; c++) {
        const int cur = c & 1;
        // prefetch next chunk's A rows into regs (LDG hides under mma)
        float4 pa[4];
        if (c + 1 < NCH) {
#pragma unroll
            for (int s = 0; s < 2; s++) {
                int row = srow + s * 64;
                const float* yp = &g_y1[(size_t)(r0 + row) * K + (c + 1) * 32 + sku * 8];
                pa[s * 2 + 0] = *(const float4*)yp;
                pa[s * 2 + 1] = *(const float4*)(yp + 4);
            }
        }
        // mma over current chunk: 3 passes x 2 ksteps
#pragma unroll
        for (int t = 0; t < 3; t++) {
            uint32_t Ab = sbase + cur * 32768 + ((t == 1) ? TB : 0);
            uint32_t Bb = sbase + cur * 32768 + 2 * TB + ((t == 2) ? TB : 0);
#pragma unroll
            for (int s = 0; s < 2; s++) {
                uint32_t a[4][4], b[2][4];
#pragma unroll
                for (int f = 0; f < 4; f++)
                    ldsm4(a[f], Ab + chunk_off(a_row[f], 2 * s + a_ke));
#pragma unroll
                for (int j = 0; j < 2; j++)
                    ldsm4(b[j], Bb + chunk_off(b_row[j], 2 * s + b_ke));
#pragma unroll
                for (int mf = 0; mf < 4; mf++) {
#pragma unroll
                    for (int nf = 0; nf < 4; nf++) {
                        uint32_t bfrag[2] = { b[nf >> 1][(nf & 1) * 2], b[nf >> 1][(nf & 1) * 2 + 1] };
                        mma_bf16(acc[mf][nf], a[mf], bfrag);
                    }
                }
            }
        }
        // store staged next chunk
        if (c + 1 < NCH) {
#pragma unroll
            for (int s = 0; s < 2; s++)
                cvt_store_A(cur ^ 1, (c + 1) * 32, pa[s * 2], pa[s * 2 + 1], srow + s * 64, sku);
            stage_B(cur ^ 1, (c + 1) * 32);
        }
        __syncthreads();
    }

    // ---- epilogue (verbatim R5): write acc + bias to sEpi ----
#pragma unroll
    for (int mf = 0; mf < 4; mf++) {
#pragma unroll
        for (int nf = 0; nf < 4; nf++) {
            int row = m_base + mf * 16 + (lane >> 2);
            int col = n_base + nf * 8 + (lane & 3) * 2;
            float2 v0 = make_float2(acc[mf][nf][0] + sBias[col], acc[mf][nf][1] + sBias[col + 1]);
            float2 v1 = make_float2(acc[mf][nf][2] + sBias[col], acc[mf][nf][3] + sBias[col + 1]);
            *(float2*)&sEpi[(size_t)row * 132 + col] = v0;
            *(float2*)&sEpi[(size_t)(row + 8) * 132 + col] = v1;
        }
    }
    __syncthreads();

    for (int c = lane; c < 128; c += 32) {
        float sum = 0.f, sq = 0.f, mx = -3.4e38f;
#pragma unroll
        for (int r = 0; r < 16; r++) {
            float v = sEpi[(size_t)(wid * 16 + r) * 132 + c];
            sum += v; sq += v * v; mx = fmaxf(mx, v);
        }
        sG[wid][c] = mx;
        atomicAdd(&sSum[c], sum);
        atomicAdd(&sSq[c], sq);
    }
    __syncthreads();

    constexpr int GPB = 128 / KGRP;
    constexpr int TPG = KGRP / 16;
    for (int idx = tid; idx < GPB * 128; idx += 256) {
        int g = idx >> 7, c = idx & 127;
        float m = -3.4e38f;
#pragma unroll
        for (int t = 0; t < TPG; t++) m = fmaxf(m, sG[g * TPG + t][c]);
        g_gmax[SC][r0 / KGRP + g][c0 + c] = m;
    }
    if (tid < 128) {
        atomicAdd(&g_sum[SLOT2][c0 + tid], (double)sSum[tid]);
        atomicAdd(&g_sq[SLOT2][c0 + tid],  (double)sSq[tid]);
    }
}

// ----------------------------- final: relu(bn2(gmax)) + transposed write -----------------------------
template<int C2, int OFF, int SLOT, int SC>
__global__ void final_kernel(float* __restrict__ outp) {
    __shared__ float tile[32][33];
    const int tx = threadIdx.x, ty = threadIdx.y;   // (32, 8)
    const int g0 = blockIdx.x * 32, c0 = blockIdx.y * 32;
    float a  = g_bnA[SLOT][c0 + tx];
    float sh = g_bnB[SLOT][c0 + tx];
#pragma unroll
    for (int j = 0; j < 4; j++) {
        int row = g0 + ty + j * 8;
        float v = g_gmax[SC][row][c0 + tx];
        tile[ty + j * 8][tx] = fmaxf(fmaf(v, a, sh), 0.f);
    }
    __syncthreads();
    int b = (g0 + tx) >> 10, s = (g0 + tx) & 1023;
#pragma unroll
    for (int j = 0; j < 4; j++) {
        int c = c0 + ty + j * 8;
        outp[((size_t)b * 640 + OFF + c) * 1024 + s] = tile[tx][ty + j * 8];
    }
}

// ----------------------------- launch -----------------------------
extern "C" void kernel_launch(void* const* d_in, const int* in_sizes, int n_in,
                              void* d_out, int out_size) {
    const float* xyz    = (const float*)d_in[0];
    const float* points = (const float*)d_in[1];
    const float* W[3][2]; const float* Bi[3][2]; const float* Ga[3][2]; const float* Be[3][2];
    for (int i = 0; i < 3; i++)
        for (int j = 0; j < 2; j++) {
            int base = 2 + i * 8 + j * 4;
            W[i][j]  = (const float*)d_in[base + 0];
            Bi[i][j] = (const float*)d_in[base + 1];
            Ga[i][j] = (const float*)d_in[base + 2];
            Be[i][j] = (const float*)d_in[base + 3];
        }

    float* out = (float*)d_out;
    const int XYZ_ELEMS = BATCH * NS * 3;
    const int PTS_ELEMS = BATCH * 640 * NS;
    bool haveXyz = (out_size >= XYZ_ELEMS + PTS_ELEMS);
    float* outpts = out + (haveXyz ? XYZ_ELEMS : 0);

    // dynamic smem: max(2 x 32KB chunk buffers, epi 128*132*4 = 67584) = 67584 (all scales)
    const int SMG = 67584;
    cudaFuncSetAttribute(gemm2_mma<64, 16, 0, 1, 0>,  cudaFuncAttributeMaxDynamicSharedMemorySize, SMG);
    cudaFuncSetAttribute(gemm2_mma<128, 32, 2, 3, 1>, cudaFuncAttributeMaxDynamicSharedMemorySize, SMG);
    cudaFuncSetAttribute(gemm2_mma<128, 64, 4, 5, 2>, cudaFuncAttributeMaxDynamicSharedMemorySize, SMG);

    // launch order: slot #4 (the profiled one) = fps (re-test the 1.4us anomaly)
    initpack_kernel<<<(BATCH * NPTS + 255) / 256, 256>>>(xyz);                 // 1
    w2prep_kernel<<<(128 * 256 + 255) / 256, 256>>>(W[1][1], 128, 256, 1);     // 2
    w2prep_kernel<<<(128 * 256 + 255) / 256, 256>>>(W[2][1], 128, 256, 2);     // 3
    fps_kernel<<<BATCH, 512>>>(xyz);                                           // 4 (profiled)
    w2prep_kernel<<<(64 * 128 + 255) / 256, 256>>>(W[0][1], 64, 128, 0);
    ballquery_kernel<<<dim3(BATCH * NS / 8, 3), 256>>>();
    if (haveXyz) copyxyz_kernel<<<(BATCH * NS + 255) / 256, 256>>>(out);

    // scale 2: Ksamp=64, C1=128, C2=256, M=524288
    gemm1_kernel<128, 6, 2, 4><<<524288 / 64, 256>>>(points, W[2][0], Bi[2][0]);
    bnfin_kernel<<<1, 256>>>(4, 128, 1.0 / 524288.0, Ga[2][0], Be[2][0]);
    gemm2_mma<128, 64, 4, 5, 2><<<dim3(524288 / 128, 2), 256, SMG>>>(Bi[2][1]);
    bnfin_kernel<<<1, 256>>>(5, 256, 1.0 / 524288.0, Ga[2][1], Be[2][1]);
    final_kernel<256, 384, 5, 2><<<dim3(256, 8), dim3(32, 8)>>>(outpts);

    // scale 0: Ksamp=16, C1=64, C2=128, M=131072
    gemm1_kernel<64, 4, 0, 0><<<131072 / 64, 256>>>(points, W[0][0], Bi[0][0]);
    bnfin_kernel<<<1, 256>>>(0, 64, 1.0 / 131072.0, Ga[0][0], Be[0][0]);
    gemm2_mma<64, 16, 0, 1, 0><<<dim3(131072 / 128, 1), 256, SMG>>>(Bi[0][1]);
    bnfin_kernel<<<1, 256>>>(1, 128, 1.0 / 131072.0, Ga[0][1], Be[0][1]);
    final_kernel<128, 0, 1, 0><<<dim3(256, 4), dim3(32, 8)>>>(outpts);

    // scale 1: Ksamp=32, C1=128, C2=256, M=262144
    gemm1_kernel<128, 5, 1, 2><<<262144 / 64, 256>>>(points, W[1][0], Bi[1][0]);
    bnfin_kernel<<<1, 256>>>(2, 128, 1.0 / 262144.0, Ga[1][0], Be[1][0]);
    gemm2_mma<128, 32, 2, 3, 1><<<dim3(262144 / 128, 2), 256, SMG>>>(Bi[1][1]);
    bnfin_kernel<<<1, 256>>>(3, 256, 1.0 / 262144.0, Ga[1][1], Be[1][1]);
    final_kernel<256, 128, 3, 1><<<dim3(256, 8), dim3(32, 8)>>>(outpts);
}

// round 11
// speedup vs baseline: 1.2191x; 1.2191x over previous
#include <cuda_runtime.h>
#include <cuda_bf16.h>
#include <cstdint>
#include <cstddef>

#define BATCH 8
#define NPTS  4096
#define NS    1024
#define DIMF  32

// ----------------------------- static device scratch -----------------------------
__device__ float4 g_pxyz[BATCH * NPTS];          // x,y,z,|p|^2
__device__ float4 g_cent[BATCH * NS];            // centers x,y,z,|c|^2
__device__ int    g_idxAll[3 * BATCH * NS * 64]; // ball-query indices, stride 64
__device__ float  g_y1[67108864];                // up to 524288 x 128
__device__ float  g_gmax[3][8192][256];          // per-scale group-max (pre-BN2)
__device__ double g_sum[6][256];
__device__ double g_sq[6][256];
__device__ float  g_bnA[6][256];
__device__ float  g_bnB[6][256];
__device__ __align__(16) __nv_bfloat16 g_w2t_hi[3][32768]; // W2^T hi split [n*K+k]
__device__ __align__(16) __nv_bfloat16 g_w2t_lo[3][32768]; // W2^T lo split

__device__ __forceinline__ uint32_t smem_u32(const void* p) {
    uint32_t a;
    asm("{ .reg .u64 t; cvta.to.shared.u64 t, %1; cvt.u32.u64 %0, t; }" : "=r"(a) : "l"(p));
    return a;
}

// ----------------------------- init: zero BN stats + pack xyz -----------------------------
__global__ void initpack_kernel(const float* __restrict__ xyz) {
    int i = blockIdx.x * 256 + threadIdx.x;
    if (i < BATCH * NPTS) {
        float x = xyz[3 * i], y = xyz[3 * i + 1], z = xyz[3 * i + 2];
        float nb = __fadd_rn(__fadd_rn(__fmul_rn(x, x), __fmul_rn(y, y)), __fmul_rn(z, z));
        g_pxyz[i] = make_float4(x, y, z, nb);
    }
    if (blockIdx.x == 0) {
        int t = threadIdx.x;
        for (int s = 0; s < 6; s++) { g_sum[s][t] = 0.0; g_sq[s][t] = 0.0; }
    }
}

// ----------------------------- W2 transpose + bf16 split prep -----------------------------
__global__ void w2prep_kernel(const float* __restrict__ W2, int K, int C2, int sc) {
    int idx = blockIdx.x * 256 + threadIdx.x;
    if (idx < K * C2) {
        int n = idx / K, k = idx % K;
        float v = W2[(size_t)k * C2 + n];
        __nv_bfloat16 h = __float2bfloat16_rn(v);
        float lo = v - __bfloat162float(h);
        g_w2t_hi[sc][idx] = h;
        g_w2t_lo[sc][idx] = __float2bfloat16_rn(lo);
    }
}

// ----------------------------- FPS v2: u64 keys, 1 barrier, smem coord LUT -----------------
// key = (bits(d) << 32) | (0xFFFFFFFF - idx): max-key == (dist >, tie -> lower idx),
// exactly jnp.argmax first-occurrence. Distance rounding chain unchanged (rn, no fma).
__global__ void __launch_bounds__(512) fps_kernel(const float* __restrict__ xyz) {
    extern __shared__ float s_lut[];              // [3 * 4096]
    float* s_cx = s_lut;
    float* s_cy = s_lut + 4096;
    float* s_cz = s_lut + 8192;
    __shared__ unsigned long long s_key[3];

    const int b = blockIdx.x;
    const float* base = xyz + (size_t)b * NPTS * 3;
    const int t = threadIdx.x, lane = t & 31;

    float px[8], py[8], pz[8], dist[8];
#pragma unroll
    for (int j = 0; j < 8; j++) {
        int p = t + j * 512;
        float x = base[3 * p], y = base[3 * p + 1], z = base[3 * p + 2];
        px[j] = x; py[j] = y; pz[j] = z;
        s_cx[p] = x; s_cy[p] = y; s_cz[p] = z;
        dist[j] = 1e10f;
    }
    if (t == 0) { s_key[0] = 0ull; s_key[1] = 0ull; s_key[2] = 0ull; }
    __syncthreads();

    float cx = base[0], cy = base[1], cz = base[2]; // first center: index 0

    for (int it = 0; it < NS; it++) {
        if (t == 0) {
            float nrm = __fadd_rn(__fadd_rn(__fmul_rn(cx, cx), __fmul_rn(cy, cy)), __fmul_rn(cz, cz));
            g_cent[b * NS + it] = make_float4(cx, cy, cz, nrm);
        }
        unsigned long long kk[8];
#pragma unroll
        for (int j = 0; j < 8; j++) {
            float dx = __fsub_rn(px[j], cx);
            float dy = __fsub_rn(py[j], cy);
            float dz = __fsub_rn(pz[j], cz);
            float d  = __fadd_rn(__fadd_rn(__fmul_rn(dx, dx), __fmul_rn(dy, dy)), __fmul_rn(dz, dz));
            float nd = fminf(dist[j], d);
            dist[j] = nd;
            kk[j] = ((unsigned long long)__float_as_uint(nd) << 32)
                  | (unsigned)(0xFFFFFFFFu - (unsigned)(t + j * 512));
        }
        // branchless max tree (depth 3)
        kk[0] = (kk[1] > kk[0]) ? kk[1] : kk[0];
        kk[2] = (kk[3] > kk[2]) ? kk[3] : kk[2];
        kk[4] = (kk[5] > kk[4]) ? kk[5] : kk[4];
        kk[6] = (kk[7] > kk[6]) ? kk[7] : kk[6];
        kk[0] = (kk[2] > kk[0]) ? kk[2] : kk[0];
        kk[4] = (kk[6] > kk[4]) ? kk[6] : kk[4];
        unsigned long long k = (kk[4] > kk[0]) ? kk[4] : kk[0];
        // warp reduce
#pragma unroll
        for (int off = 16; off > 0; off >>= 1) {
            unsigned long long ok = __shfl_xor_sync(0xffffffffu, k, off);
            k = (ok > k) ? ok : k;
        }
        if (lane == 0) atomicMax(&s_key[it % 3], k);
        __syncthreads();
        unsigned long long kb = s_key[it % 3];
        if (t == 0) s_key[(it + 2) % 3] = 0ull;   // safe: next atomics to that slot are 2 barriers away
        int idx = (int)(0xFFFFFFFFu - (unsigned)kb);
        cx = s_cx[idx]; cy = s_cy[idx]; cz = s_cz[idx];
    }
}

// copy new_xyz from g_cent into d_out
__global__ void copyxyz_kernel(float* __restrict__ out) {
    int i = blockIdx.x * 256 + threadIdx.x;
    if (i < BATCH * NS) {
        float4 c = g_cent[i];
        out[3 * i] = c.x; out[3 * i + 1] = c.y; out[3 * i + 2] = c.z;
    }
}

// ----------------------------- ball query (3 scales, unchanged) -----------------------------
__global__ void __launch_bounds__(256) ballquery_kernel() {
    const int scale = blockIdx.y;
    const float r2 = (scale == 0) ? 0.01f : (scale == 1) ? 0.04f : 0.16f;
    const int K = 16 << scale;
    const int t = threadIdx.x, lane = t & 31, warp = t >> 5;
    const int g = blockIdx.x * 8 + warp;
    const int b = g >> 10;
    float4 c = g_cent[g];
    int* out = g_idxAll + scale * (BATCH * NS * 64) + g * 64;
    const float4* P = g_pxyz + ((size_t)b << 12);

    int cnt = 0, firstIdx = 0;
    for (int ch = 0; ch < NPTS / 32; ch++) {
        int p = (ch << 5) + lane;
        float4 q = P[p];
        float dot = __fadd_rn(__fadd_rn(__fmul_rn(c.x, q.x), __fmul_rn(c.y, q.y)), __fmul_rn(c.z, q.z));
        float d = __fsub_rn(__fadd_rn(c.w, q.w), __fadd_rn(dot, dot));
        bool ok = (d <= r2);
        unsigned mask = __ballot_sync(0xffffffffu, ok);
        if (mask) {
            if (cnt == 0) firstIdx = (ch << 5) + (__ffs(mask) - 1);
            if (ok) {
                int pos = cnt + __popc(mask & ((1u << lane) - 1u));
                if (pos < K) out[pos] = p;
            }
            cnt += __popc(mask);
            if (cnt >= K) break;
        }
    }
    if (cnt < K) {
        for (int i = cnt + lane; i < K; i += 32) out[i] = firstIdx;
    }
}

// ----------------------------- GEMM1: fused gather + feat@W1 + b1, BN stats (R5 version) ------
template<int C1, int KLOG, int SCALE, int SLOT>
__global__ void __launch_bounds__(256) gemm1_kernel(const float* __restrict__ points,
                                                    const float* __restrict__ W,
                                                    const float* __restrict__ bias) {
    constexpr int KS = 1 << KLOG;
    constexpr int CT = C1 / 4;
    constexpr int RG = 256 / CT;
    constexpr int RT = 64 / RG;
    __shared__ float sA[64][36];
    __shared__ float sW[35][C1];
    __shared__ float sBias[C1];

    const int tid = threadIdx.x;
    const int r0 = blockIdx.x * 64;

    {
        int row = tid >> 2, sub = tid & 3;
        int gr = r0 + row;
        int b = gr >> (10 + KLOG);
        int s = (gr >> KLOG) & 1023;
        int k = gr & (KS - 1);
        int g = (b << 10) + s;
        int idx = g_idxAll[SCALE * (BATCH * NS * 64) + g * 64 + k];
        if (sub == 0) {
            float4 p = g_pxyz[(b << 12) + idx];
            float4 c = g_cent[g];
            sA[row][0] = p.x - c.x; sA[row][1] = p.y - c.y; sA[row][2] = p.z - c.z;
        }
        const float4* p4 = (const float4*)(points + ((((size_t)(b << 12)) + idx) << 5));
        float4 v0 = p4[sub * 2], v1 = p4[sub * 2 + 1];
        int cb = 3 + sub * 8;
        sA[row][cb + 0] = v0.x; sA[row][cb + 1] = v0.y; sA[row][cb + 2] = v0.z; sA[row][cb + 3] = v0.w;
        sA[row][cb + 4] = v1.x; sA[row][cb + 5] = v1.y; sA[row][cb + 6] = v1.z; sA[row][cb + 7] = v1.w;
    }
    for (int i = tid; i < 35 * C1; i += 256) sW[i / C1][i % C1] = W[i];
    if (tid < C1) sBias[tid] = bias[tid];
    __syncthreads();

    const int tx = tid % CT, ty = tid / CT;
    float acc[RT][4];
#pragma unroll
    for (int i = 0; i < RT; i++) { acc[i][0] = 0.f; acc[i][1] = 0.f; acc[i][2] = 0.f; acc[i][3] = 0.f; }

#pragma unroll
    for (int k = 0; k < 35; k++) {
        float4 w = *(const float4*)&sW[k][tx * 4];
#pragma unroll
        for (int i = 0; i < RT; i++) {
            float a = sA[ty * RT + i][k];
            acc[i][0] = fmaf(a, w.x, acc[i][0]);
            acc[i][1] = fmaf(a, w.y, acc[i][1]);
            acc[i][2] = fmaf(a, w.z, acc[i][2]);
            acc[i][3] = fmaf(a, w.w, acc[i][3]);
        }
    }

    float4 bb = *(const float4*)&sBias[tx * 4];
    float lsum[4] = {0.f, 0.f, 0.f, 0.f}, lsq[4] = {0.f, 0.f, 0.f, 0.f};
#pragma unroll
    for (int i = 0; i < RT; i++) {
        float4 v;
        v.x = acc[i][0] + bb.x; v.y = acc[i][1] + bb.y;
        v.z = acc[i][2] + bb.z; v.w = acc[i][3] + bb.w;
        *(float4*)&g_y1[((size_t)(r0 + ty * RT + i)) * C1 + tx * 4] = v;
        lsum[0] += v.x; lsq[0] += v.x * v.x;
        lsum[1] += v.y; lsq[1] += v.y * v.y;
        lsum[2] += v.z; lsq[2] += v.z * v.z;
        lsum[3] += v.w; lsq[3] += v.w * v.w;
    }
    __syncthreads();
    float* csum = &sA[0][0];
    float* csq  = csum + C1;
    if (tid < C1) { csum[tid] = 0.f; csq[tid] = 0.f; }
    __syncthreads();
#pragma unroll
    for (int j = 0; j < 4; j++) {
        atomicAdd(&csum[tx * 4 + j], lsum[j]);
        atomicAdd(&csq[tx * 4 + j], lsq[j]);
    }
    __syncthreads();
    if (tid < C1) {
        atomicAdd(&g_sum[SLOT][tid], (double)csum[tid]);
        atomicAdd(&g_sq[SLOT][tid],  (double)csq[tid]);
    }
}

// ----------------------------- BN finalize -----------------------------
__global__ void bnfin_kernel(int slot, int C, double invCount,
                             const float* __restrict__ gamma,
                             const float* __restrict__ beta) {
    int c = threadIdx.x;
    if (c < C) {
        double mean = g_sum[slot][c] * invCount;
        double var  = g_sq[slot][c] * invCount - mean * mean;
        float a = gamma[c] * rsqrtf((float)var + 1e-5f);
        g_bnA[slot][c] = a;
        g_bnB[slot][c] = beta[c] - (float)mean * a;
    }
}

// ----------------------------- GEMM2 via mma.sync bf16x3 (NT=1, R5 champion version) -----------
__device__ __forceinline__ void mma_bf16(float* c, const uint32_t* a, const uint32_t* b) {
    asm volatile("mma.sync.aligned.m16n8k16.row.col.f32.bf16.bf16.f32 "
                 "{%0,%1,%2,%3}, {%4,%5,%6,%7}, {%8,%9}, {%0,%1,%2,%3};"
                 : "+f"(c[0]), "+f"(c[1]), "+f"(c[2]), "+f"(c[3])
                 : "r"(a[0]), "r"(a[1]), "r"(a[2]), "r"(a[3]), "r"(b[0]), "r"(b[1]));
}
__device__ __forceinline__ void ldsm4(uint32_t* r, uint32_t addr) {
    asm volatile("ldmatrix.sync.aligned.m8n8.x4.shared.b16 {%0,%1,%2,%3}, [%4];"
                 : "=r"(r[0]), "=r"(r[1]), "=r"(r[2]), "=r"(r[3]) : "r"(addr));
}

template<int K, int KGRP, int SLOT1, int SLOT2, int SC>
__global__ void __launch_bounds__(256) gemm2_mma(const float* __restrict__ bias2) {
    extern __shared__ char smem[];
    constexpr int TILE = 128 * K * 2;   // bytes per bf16 tile
    constexpr int RU = K / 8;           // 16B units per row
    char* A_HI = smem;
    char* A_LO = smem + TILE;
    char* B_HI = smem + 2 * TILE;
    char* B_LO = smem + 3 * TILE;
    float* sEpi = (float*)smem;         // [128][132], aliases tiles post-MMA

    __shared__ float sBias[128];
    __shared__ float sG[8][128];
    __shared__ float sSum[128];
    __shared__ float sSq[128];

    const int tid = threadIdx.x;
    const int wid = tid >> 5, lane = tid & 31;
    const int r0 = blockIdx.x * 128;
    const int c0 = blockIdx.y * 128;

    if (tid < 128) { sBias[tid] = bias2[c0 + tid]; sSum[tid] = 0.f; sSq[tid] = 0.f; }

    // ---- stage A (BN1+ReLU+split) and B (pre-split) into swizzled smem ----
    union Pack { __nv_bfloat16 h[8]; uint4 u; };
#pragma unroll
    for (int i = 0; i < 128 * RU / 256; i++) {
        int idx = tid + i * 256;
        int row = idx / RU, ku = idx % RU;
        int k = ku * 8;
        uint32_t off = (uint32_t)row * (K * 2) + (((ku & ~7) | ((ku ^ (row & 7)) & 7)) << 4);
        float4 v0 = *(const float4*)&g_y1[(size_t)(r0 + row) * K + k];
        float4 v1 = *(const float4*)&g_y1[(size_t)(r0 + row) * K + k + 4];
        float f[8] = {v0.x, v0.y, v0.z, v0.w, v1.x, v1.y, v1.z, v1.w};
        Pack ph, pl;
#pragma unroll
        for (int j = 0; j < 8; j++) {
            float v = fmaxf(fmaf(f[j], g_bnA[SLOT1][k + j], g_bnB[SLOT1][k + j]), 0.f);
            __nv_bfloat16 h = __float2bfloat16_rn(v);
            ph.h[j] = h;
            pl.h[j] = __float2bfloat16_rn(v - __bfloat162float(h));
        }
        *(uint4*)(A_HI + off) = ph.u;
        *(uint4*)(A_LO + off) = pl.u;
        *(uint4*)(B_HI + off) = *(const uint4*)&g_w2t_hi[SC][(size_t)(c0 + row) * K + k];
        *(uint4*)(B_LO + off) = *(const uint4*)&g_w2t_lo[SC][(size_t)(c0 + row) * K + k];
    }
    __syncthreads();

    // ---- warp tiling: 2(M) x 4(N) warps, 64x32 per warp ----
    const int wm = wid >> 2, wn = wid & 3;
    const int m_base = wm * 64, n_base = wn * 32;
    const uint32_t sbase = smem_u32(smem);
    const int mat = lane >> 3, r8 = lane & 7;

    int a_row[4], b_row[2];
    const int a_ke = mat >> 1;
    const int b_ke = mat & 1;
#pragma unroll
    for (int f = 0; f < 4; f++) a_row[f] = m_base + f * 16 + (mat & 1) * 8 + r8;
#pragma unroll
    for (int j = 0; j < 2; j++) b_row[j] = n_base + 16 * j + (mat >> 1) * 8 + r8;

    float acc[4][4][4];
#pragma unroll
    for (int mf = 0; mf < 4; mf++)
#pragma unroll
        for (int nf = 0; nf < 4; nf++)
#pragma unroll
            for (int q = 0; q < 4; q++) acc[mf][nf][q] = 0.f;

#pragma unroll 1
    for (int t = 0; t < 3; t++) {
        uint32_t Ab = sbase + ((t == 1) ? TILE : 0);
        uint32_t Bb = sbase + ((t == 2) ? 3 * TILE : 2 * TILE);
#pragma unroll
        for (int k = 0; k < K; k += 16) {
            int ku0 = k >> 3;
            uint32_t a[4][4], b[2][4];
#pragma unroll
            for (int f = 0; f < 4; f++) {
                int ku = ku0 + a_ke;
                uint32_t pu = (ku & ~7) | ((ku ^ (a_row[f] & 7)) & 7);
                ldsm4(a[f], Ab + (uint32_t)a_row[f] * (K * 2) + (pu << 4));
            }
#pragma unroll
            for (int j = 0; j < 2; j++) {
                int ku = ku0 + b_ke;
                uint32_t pu = (ku & ~7) | ((ku ^ (b_row[j] & 7)) & 7);
                ldsm4(b[j], Bb + (uint32_t)b_row[j] * (K * 2) + (pu << 4));
            }
#pragma unroll
            for (int mf = 0; mf < 4; mf++) {
#pragma unroll
                for (int nf = 0; nf < 4; nf++) {
                    uint32_t bfrag[2] = { b[nf >> 1][(nf & 1) * 2], b[nf >> 1][(nf & 1) * 2 + 1] };
                    mma_bf16(acc[mf][nf], a[mf], bfrag);
                }
            }
        }
    }
    __syncthreads();   // tiles dead; reuse smem as sEpi

    // ---- write acc + bias to sEpi ----
#pragma unroll
    for (int mf = 0; mf < 4; mf++) {
#pragma unroll
        for (int nf = 0; nf < 4; nf++) {
            int row = m_base + mf * 16 + (lane >> 2);
            int col = n_base + nf * 8 + (lane & 3) * 2;
            float2 v0 = make_float2(acc[mf][nf][0] + sBias[col], acc[mf][nf][1] + sBias[col + 1]);
            float2 v1 = make_float2(acc[mf][nf][2] + sBias[col], acc[mf][nf][3] + sBias[col + 1]);
            *(float2*)&sEpi[(size_t)row * 132 + col] = v0;
            *(float2*)&sEpi[(size_t)(row + 8) * 132 + col] = v1;
        }
    }
    __syncthreads();

    // ---- per-warp 16-row stats over all 128 cols ----
    for (int c = lane; c < 128; c += 32) {
        float sum = 0.f, sq = 0.f, mx = -3.4e38f;
#pragma unroll
        for (int r = 0; r < 16; r++) {
            float v = sEpi[(size_t)(wid * 16 + r) * 132 + c];
            sum += v; sq += v * v; mx = fmaxf(mx, v);
        }
        sG[wid][c] = mx;
        atomicAdd(&sSum[c], sum);
        atomicAdd(&sSq[c], sq);
    }
    __syncthreads();

    // ---- merges ----
    constexpr int GPB = 128 / KGRP;
    constexpr int TPG = KGRP / 16;
    for (int idx = tid; idx < GPB * 128; idx += 256) {
        int g = idx >> 7, c = idx & 127;
        float m = -3.4e38f;
#pragma unroll
        for (int t = 0; t < TPG; t++) m = fmaxf(m, sG[g * TPG + t][c]);
        g_gmax[SC][r0 / KGRP + g][c0 + c] = m;
    }
    if (tid < 128) {
        atomicAdd(&g_sum[SLOT2][c0 + tid], (double)sSum[tid]);
        atomicAdd(&g_sq[SLOT2][c0 + tid],  (double)sSq[tid]);
    }
}

// ----------------------------- final: relu(bn2(gmax)) + transposed write -----------------------------
template<int C2, int OFF, int SLOT, int SC>
__global__ void final_kernel(float* __restrict__ outp) {
    __shared__ float tile[32][33];
    const int tx = threadIdx.x, ty = threadIdx.y;   // (32, 8)
    const int g0 = blockIdx.x * 32, c0 = blockIdx.y * 32;
    float a  = g_bnA[SLOT][c0 + tx];
    float sh = g_bnB[SLOT][c0 + tx];
#pragma unroll
    for (int j = 0; j < 4; j++) {
        int row = g0 + ty + j * 8;
        float v = g_gmax[SC][row][c0 + tx];
        tile[ty + j * 8][tx] = fmaxf(fmaf(v, a, sh), 0.f);
    }
    __syncthreads();
    int b = (g0 + tx) >> 10, s = (g0 + tx) & 1023;
#pragma unroll
    for (int j = 0; j < 4; j++) {
        int c = c0 + ty + j * 8;
        outp[((size_t)b * 640 + OFF + c) * 1024 + s] = tile[tx][ty + j * 8];
    }
}

// ----------------------------- launch -----------------------------
extern "C" void kernel_launch(void* const* d_in, const int* in_sizes, int n_in,
                              void* d_out, int out_size) {
    const float* xyz    = (const float*)d_in[0];
    const float* points = (const float*)d_in[1];
    const float* W[3][2]; const float* Bi[3][2]; const float* Ga[3][2]; const float* Be[3][2];
    for (int i = 0; i < 3; i++)
        for (int j = 0; j < 2; j++) {
            int base = 2 + i * 8 + j * 4;
            W[i][j]  = (const float*)d_in[base + 0];
            Bi[i][j] = (const float*)d_in[base + 1];
            Ga[i][j] = (const float*)d_in[base + 2];
            Be[i][j] = (const float*)d_in[base + 3];
        }

    float* out = (float*)d_out;
    const int XYZ_ELEMS = BATCH * NS * 3;
    const int PTS_ELEMS = BATCH * 640 * NS;
    bool haveXyz = (out_size >= XYZ_ELEMS + PTS_ELEMS);
    float* outpts = out + (haveXyz ? XYZ_ELEMS : 0);

    // dynamic smem: gemm2 max(4 bf16 tiles, epi 128*132*4 = 67584); fps LUT 48KB
    const int EPI = 128 * 132 * 4;
    const int SM0 = (4 * 128 * 64 * 2 > EPI) ? 4 * 128 * 64 * 2 : EPI;    // K=64  -> 67584
    const int SM1 = (4 * 128 * 128 * 2 > EPI) ? 4 * 128 * 128 * 2 : EPI;  // K=128 -> 131072
    const int SMF = 3 * 4096 * 4;                                          // 49152
    cudaFuncSetAttribute(gemm2_mma<64, 16, 0, 1, 0>,  cudaFuncAttributeMaxDynamicSharedMemorySize, SM0);
    cudaFuncSetAttribute(gemm2_mma<128, 32, 2, 3, 1>, cudaFuncAttributeMaxDynamicSharedMemorySize, SM1);
    cudaFuncSetAttribute(gemm2_mma<128, 64, 4, 5, 2>, cudaFuncAttributeMaxDynamicSharedMemorySize, SM1);
    cudaFuncSetAttribute(fps_kernel, cudaFuncAttributeMaxDynamicSharedMemorySize, SMF);

    // launch order: slot #4 (the profiled one) = fps (verify the improvement)
    initpack_kernel<<<(BATCH * NPTS + 255) / 256, 256>>>(xyz);                 // 1
    w2prep_kernel<<<(128 * 256 + 255) / 256, 256>>>(W[1][1], 128, 256, 1);     // 2
    w2prep_kernel<<<(128 * 256 + 255) / 256, 256>>>(W[2][1], 128, 256, 2);     // 3
    fps_kernel<<<BATCH, 512, SMF>>>(xyz);                                      // 4 (profiled)
    w2prep_kernel<<<(64 * 128 + 255) / 256, 256>>>(W[0][1], 64, 128, 0);
    ballquery_kernel<<<dim3(BATCH * NS / 8, 3), 256>>>();
    if (haveXyz) copyxyz_kernel<<<(BATCH * NS + 255) / 256, 256>>>(out);

    // scale 2: Ksamp=64, C1=128, C2=256, M=524288
    gemm1_kernel<128, 6, 2, 4><<<524288 / 64, 256>>>(points, W[2][0], Bi[2][0]);
    bnfin_kernel<<<1, 256>>>(4, 128, 1.0 / 524288.0, Ga[2][0], Be[2][0]);
    gemm2_mma<128, 64, 4, 5, 2><<<dim3(524288 / 128, 2), 256, SM1>>>(Bi[2][1]);
    bnfin_kernel<<<1, 256>>>(5, 256, 1.0 / 524288.0, Ga[2][1], Be[2][1]);
    final_kernel<256, 384, 5, 2><<<dim3(256, 8), dim3(32, 8)>>>(outpts);

    // scale 0: Ksamp=16, C1=64, C2=128, M=131072
    gemm1_kernel<64, 4, 0, 0><<<131072 / 64, 256>>>(points, W[0][0], Bi[0][0]);
    bnfin_kernel<<<1, 256>>>(0, 64, 1.0 / 131072.0, Ga[0][0], Be[0][0]);
    gemm2_mma<64, 16, 0, 1, 0><<<dim3(131072 / 128, 1), 256, SM0>>>(Bi[0][1]);
    bnfin_kernel<<<1, 256>>>(1, 128, 1.0 / 131072.0, Ga[0][1], Be[0][1]);
    final_kernel<128, 0, 1, 0><<<dim3(256, 4), dim3(32, 8)>>>(outpts);

    // scale 1: Ksamp=32, C1=128, C2=256, M=262144
    gemm1_kernel<128, 5, 1, 2><<<262144 / 64, 256>>>(points, W[1][0], Bi[1][0]);
    bnfin_kernel<<<1, 256>>>(2, 128, 1.0 / 262144.0, Ga[1][0], Be[1][0]);
    gemm2_mma<128, 32, 2, 3, 1><<<dim3(262144 / 128, 2), 256, SM1>>>(Bi[1][1]);
    bnfin_kernel<<<1, 256>>>(3, 256, 1.0 / 262144.0, Ga[1][1], Be[1][1]);
    final_kernel<256, 128, 3, 1><<<dim3(256, 8), dim3(32, 8)>>>(outpts);
}